// round 12
// baseline (speedup 1.0000x reference)
#include <cuda_runtime.h>

// SE block, persistent kernel, 152 blocks (1/SM) x 1024 threads.
// Both streaming phases ride cp.async.bulk:
//   Phase 1: gmem->smem bulk loads (evict_last: pin x in L2), reduce in smem.
//   Phase 3: gmem->smem bulk loads (evict_first) -> multiply -> smem->gmem
//            bulk STORES (evict_first: out must not evict x from L2).
// 4-plane (50KB) buffers, 14 iters/phase. 2 load + 2 store buffers.
// Warp<->plane mapping is exact: 98 f4/warp x 8 warps = 1 plane.
// Per-batch arrival counters (replay-safe mod-256) instead of a global barrier.

#define C        256
#define BOT      32
#define HW       3136
#define HW4      784
#define PLANE_BYTES 12544
#define BC       8192
#define GRID     152
#define NTHREADS 1024
#define PPBUF    4                    // planes per buffer
#define BUF_F4   (PPBUF * HW4)        // 3136 float4
#define PH_ITERS 14                   // ceil(54/4)
#define TOT_ITERS (2 * PH_ITERS)

struct __align__(128) Smem {
    float4 lbuf[2][BUF_F4];           // 100352 B load ring
    float4 sbuf[2][BUF_F4];           // 100352 B store ring
    unsigned long long mbar[2];
    float wsum[2][4][8];              // [it&1][plane_in_buf][warp_in_group]
    float psum[60];                   // per-plane sums for this block
    float s[2][C];
    float h[2][BOT];
    float g[56];
};

__device__ float d_s[BC];
__device__ unsigned int d_cnt[32];    // per-batch counters (never reset)

__device__ __forceinline__ unsigned smem_u32(const void* p) {
    return (unsigned)__cvta_generic_to_shared(p);
}
__device__ __forceinline__ void mbar_init(unsigned a, unsigned cnt) {
    asm volatile("mbarrier.init.shared.b64 [%0], %1;" :: "r"(a), "r"(cnt) : "memory");
}
__device__ __forceinline__ void mbar_expect_tx(unsigned a, unsigned bytes) {
    asm volatile("mbarrier.arrive.expect_tx.shared.b64 _, [%0], %1;"
                 :: "r"(a), "r"(bytes) : "memory");
}
__device__ __forceinline__ void bulk_ld(unsigned dst, const void* src,
                                        unsigned bytes, unsigned bar,
                                        unsigned long long pol) {
    asm volatile(
        "cp.async.bulk.shared::cluster.global.mbarrier::complete_tx::bytes"
        ".L2::cache_hint [%0], [%1], %2, [%3], %4;"
        :: "r"(dst), "l"(src), "r"(bytes), "r"(bar), "l"(pol) : "memory");
}
__device__ __forceinline__ void bulk_st(void* dst, unsigned src,
                                        unsigned bytes, unsigned long long pol) {
    asm volatile(
        "cp.async.bulk.global.shared::cta.bulk_group.L2::cache_hint "
        "[%0], [%1], %2, %3;"
        :: "l"(dst), "r"(src), "r"(bytes), "l"(pol) : "memory");
}
__device__ __forceinline__ void mbar_wait(unsigned a, unsigned parity) {
    asm volatile(
        "{\n\t.reg .pred P;\n"
        "W%=:\n\t"
        "mbarrier.try_wait.parity.shared.b64 P, [%0], %1;\n\t"
        "@P bra D%=;\n\t"
        "bra W%=;\n"
        "D%=:\n\t}"
        :: "r"(a), "r"(parity) : "memory");
}

__global__ void __launch_bounds__(NTHREADS, 1) se_fused_kernel(
    const float* __restrict__ x,
    const float* __restrict__ w1, const float* __restrict__ b1,
    const float* __restrict__ w2, const float* __restrict__ b2,
    float* __restrict__ out)
{
    extern __shared__ unsigned char smem_raw[];
    Smem* sm = reinterpret_cast<Smem*>(smem_raw);

    const int tid  = threadIdx.x;
    const int warp = tid >> 5;
    const int lane = tid & 31;
    const int bid  = blockIdx.x;

    const int p0 = (int)(((long long)bid * BC) / GRID);
    const int p1 = (int)(((long long)(bid + 1) * BC) / GRID);
    const int nk = p1 - p0;                    // 53 or 54 planes
    const int b0 = p0 >> 8;
    const int nb = ((p1 - 1) >> 8) - b0 + 1;   // 1 or 2 batches
    const int n0 = min((b0 + 1) * C, p1) - p0;
    const int n1 = nk - n0;

    unsigned long long pol_last, pol_first;
    asm("createpolicy.fractional.L2::evict_last.b64 %0;"  : "=l"(pol_last));
    asm("createpolicy.fractional.L2::evict_first.b64 %0;" : "=l"(pol_first));

    // helper: issue load for global iteration it (phase from it)
    auto issue_load = [&](int it) {
        if (it >= TOT_ITERS) return;
        const bool ph1 = it < PH_ITERS;
        const int rel = ph1 ? it : it - PH_ITERS;
        const int base = rel * PPBUF;
        if (base >= nk) return;
        int planes = nk - base; if (planes > PPBUF) planes = PPBUF;
        const unsigned bytes = (unsigned)planes * PLANE_BYTES;
        const int slot = it & 1;
        const unsigned bar = smem_u32(&sm->mbar[slot]);
        mbar_expect_tx(bar, bytes);
        bulk_ld(smem_u32(&sm->lbuf[slot][0]),
                x + (size_t)(p0 + base) * HW, bytes, bar,
                ph1 ? pol_last : pol_first);
    };

    if (tid == 0) {
        mbar_init(smem_u32(&sm->mbar[0]), 1);
        mbar_init(smem_u32(&sm->mbar[1]), 1);
    }
    if (tid < 60) sm->psum[tid] = 0.0f;
    __syncthreads();
    if (tid == 0) { issue_load(0); issue_load(1); }

    // =================== Phase 1: pipelined reduce =====================
    for (int it = 0; it < PH_ITERS; ++it) {
        const int slot = it & 1;
        const int base = it * PPBUF;
        int planes = nk - base; if (planes > PPBUF) planes = PPBUF;
        const int nf4 = planes * HW4;

        mbar_wait(smem_u32(&sm->mbar[slot]), (unsigned)((it >> 1) & 1));
        const float4* __restrict__ bp = sm->lbuf[slot];

        // warp w covers f4 [w*98, w*98+98); 8 warps == exactly 1 plane
        const int wbase = warp * 98;
        float acc = 0.0f;
        {
            int i = wbase + lane;
            if (i < nf4) { float4 v = bp[i]; acc += (v.x + v.y) + (v.z + v.w); }
            i += 32;
            if (i < nf4) { float4 v = bp[i]; acc += (v.x + v.y) + (v.z + v.w); }
            i += 32;
            if (i < nf4) { float4 v = bp[i]; acc += (v.x + v.y) + (v.z + v.w); }
            i = wbase + 96 + lane;
            if (lane < 2 && i < nf4) {
                float4 v = bp[i]; acc += (v.x + v.y) + (v.z + v.w);
            }
        }
        #pragma unroll
        for (int o = 16; o > 0; o >>= 1)
            acc += __shfl_xor_sync(0xffffffffu, acc, o);
        if (lane == 0) sm->wsum[it & 1][warp >> 3][warp & 7] = acc;
        __syncthreads();                  // buffer consumed + wsum visible
        if (tid == 0) issue_load(it + 2);
        if (tid < 4) {                    // combine 8 warp sums -> plane sum
            const float* w8 = sm->wsum[it & 1][tid];
            float s = ((w8[0] + w8[1]) + (w8[2] + w8[3]))
                    + ((w8[4] + w8[5]) + (w8[6] + w8[7]));
            sm->psum[base + tid] += s;
        }
    }
    __syncthreads();
    if (tid < nk) d_s[p0 + tid] = sm->psum[tid] * (1.0f / (float)HW);
    __threadfence();
    __syncthreads();

    // ============ Per-batch arrive + wait (replay-safe, mod-256) ========
    if (tid == 0) {
        atomicAdd(&d_cnt[b0], (unsigned)n0);
        if (n1 > 0) atomicAdd(&d_cnt[b0 + 1], (unsigned)n1);
        volatile unsigned int* vc = d_cnt;
        while (vc[b0] & 255u) __nanosleep(32);
        if (n1 > 0)
            while (vc[b0 + 1] & 255u) __nanosleep(32);
        __threadfence();
    }
    __syncthreads();

    // =================== Phase 2: tiny MLP =============================
    for (int idx = tid; idx < nb * C; idx += NTHREADS)
        sm->s[idx >> 8][idx & 255] = d_s[b0 * C + idx];
    __syncthreads();

    for (int j = warp; j < nb * BOT; j += 32) {
        const int bi = j >> 5, o = j & 31;
        const float* __restrict__ w1row = w1 + o * C;
        float acc = 0.0f;
        #pragma unroll
        for (int k = 0; k < 8; k++) {
            const int c = lane + 32 * k;
            acc = fmaf(sm->s[bi][c], __ldg(w1row + c), acc);
        }
        #pragma unroll
        for (int off = 16; off > 0; off >>= 1)
            acc += __shfl_xor_sync(0xffffffffu, acc, off);
        if (lane == 0) sm->h[bi][o] = fmaxf(acc + __ldg(b1 + o), 0.0f);
    }
    __syncthreads();

    if (tid < nk) {
        const int plane = p0 + tid;
        const int c = plane & 255;
        const int bi = (plane >> 8) - b0;
        const float* __restrict__ wrow = w2 + c * BOT;
        float acc = __ldg(b2 + c);
        #pragma unroll
        for (int o = 0; o < BOT; o++)
            acc = fmaf(sm->h[bi][o], __ldg(wrow + o), acc);
        sm->g[tid] = 1.0f / (1.0f + __expf(-acc));
    }
    __syncthreads();

    // =================== Phase 3: pipelined scale + bulk store ==========
    for (int git = PH_ITERS; git < TOT_ITERS; ++git) {
        const int slot = git & 1;
        const int rel  = git - PH_ITERS;
        const int base = rel * PPBUF;
        if (base >= nk) break;
        int planes = nk - base; if (planes > PPBUF) planes = PPBUF;
        const int nf4 = planes * HW4;

        mbar_wait(smem_u32(&sm->mbar[slot]), (unsigned)((git >> 1) & 1));

        if (git >= PH_ITERS + 2) {
            // store slot (git&1) was bulk-stored 2 iters ago; ensure drained
            if (tid == 0)
                asm volatile("cp.async.bulk.wait_group 1;" ::: "memory");
            __syncthreads();
        }

        const float4* __restrict__ lp = sm->lbuf[slot];
        float4* __restrict__ sp = sm->sbuf[slot];
        {
            int i = tid;
            if (i < nf4) {
                float4 v = lp[i];
                const float g = sm->g[base + (i / HW4)];
                v.x *= g; v.y *= g; v.z *= g; v.w *= g;
                sp[i] = v;
            }
            i = tid + NTHREADS;
            if (i < nf4) {
                float4 v = lp[i];
                const float g = sm->g[base + (i / HW4)];
                v.x *= g; v.y *= g; v.z *= g; v.w *= g;
                sp[i] = v;
            }
            i = tid + 2 * NTHREADS;
            if (i < nf4) {
                float4 v = lp[i];
                const float g = sm->g[base + (i / HW4)];
                v.x *= g; v.y *= g; v.z *= g; v.w *= g;
                sp[i] = v;
            }
            i = tid + 3 * NTHREADS;
            if (i < nf4) {
                float4 v = lp[i];
                const float g = sm->g[base + (i / HW4)];
                v.x *= g; v.y *= g; v.z *= g; v.w *= g;
                sp[i] = v;
            }
        }
        __syncthreads();                   // sbuf ready, lbuf consumed
        if (tid == 0) {
            asm volatile("fence.proxy.async;" ::: "memory");
            bulk_st(out + (size_t)(p0 + base) * HW,
                    smem_u32(&sm->sbuf[slot][0]),
                    (unsigned)planes * PLANE_BYTES, pol_first);
            asm volatile("cp.async.bulk.commit_group;" ::: "memory");
            issue_load(git + 2);
        }
    }
    if (tid == 0)
        asm volatile("cp.async.bulk.wait_group 0;" ::: "memory");
}

extern "C" void kernel_launch(void* const* d_in, const int* in_sizes, int n_in,
                              void* d_out, int out_size) {
    const float* x  = (const float*)d_in[0];
    const float* w1 = (const float*)d_in[1];
    const float* b1 = (const float*)d_in[2];
    const float* w2 = (const float*)d_in[3];
    const float* b2 = (const float*)d_in[4];
    float* out = (float*)d_out;

    static bool attr_set = false;
    if (!attr_set) {
        cudaFuncSetAttribute(se_fused_kernel,
                             cudaFuncAttributeMaxDynamicSharedMemorySize,
                             (int)sizeof(Smem));
        attr_set = true;
    }
    se_fused_kernel<<<GRID, NTHREADS, sizeof(Smem)>>>(x, w1, b1, w2, b2, out);
}